// round 5
// baseline (speedup 1.0000x reference)
#include <cuda_runtime.h>

#define N_NODES 100000
#define E_MAX   1600000
#define D_IN    128
#define D_H     64
#define D_OUT   16
#define SLOT    80          // fixed CSR slots per node (Poisson(16): P(deg>=80)~1e-28)

// ---- packed f32x2 helpers (sm_103a dual-lane fp32 pipe) ----
#define FFMA2(d, a, b, c) \
    asm("fma.rn.f32x2 %0, %1, %2, %3;" : "=l"(d) : "l"(a), "l"(b), "l"(c))
#define FADD2(d, a, b) \
    asm("add.rn.f32x2 %0, %1, %2;" : "=l"(d) : "l"(a), "l"(b))

__device__ __forceinline__ unsigned long long pack2(float lo, float hi) {
    unsigned long long r;
    asm("mov.b64 %0, {%1, %2};" : "=l"(r) : "f"(lo), "f"(hi));
    return r;
}
__device__ __forceinline__ void unpack2(unsigned long long v, float& lo, float& hi) {
    asm("mov.b64 {%0, %1}, %2;" : "=f"(lo), "=f"(hi) : "l"(v));
}

// ---- scratch (__device__ globals: allocation-free rule) ----
// g_cnt arrives zeroed (zero-init at load; re-zeroed by k_agg2 every run).
__device__ int   g_cnt[N_NODES];
__device__ int   g_csr[(size_t)N_NODES * SLOT];
__device__ float g_hs1[(size_t)N_NODES * D_H];
__device__ float g_hs2[(size_t)N_NODES * D_OUT];

// ================= single-pass slotted CSR build =================
// rank = atomicAdd count; entry lands directly in its node's slot row.

__global__ void k_build(const int* __restrict__ src, const int* __restrict__ dst, int E) {
    int b = (blockIdx.x * blockDim.x + threadIdx.x) * 4;
    if (b + 3 < E && ((E & 3) == 0)) {
        int4 s = *(const int4*)&src[b];
        int4 d = *(const int4*)&dst[b];
        int r0 = atomicAdd(&g_cnt[d.x], 1);
        int r1 = atomicAdd(&g_cnt[d.y], 1);
        int r2 = atomicAdd(&g_cnt[d.z], 1);
        int r3 = atomicAdd(&g_cnt[d.w], 1);
        if (r0 < SLOT) g_csr[(size_t)d.x * SLOT + r0] = s.x;
        if (r1 < SLOT) g_csr[(size_t)d.y * SLOT + r1] = s.y;
        if (r2 < SLOT) g_csr[(size_t)d.z * SLOT + r2] = s.z;
        if (r3 < SLOT) g_csr[(size_t)d.w * SLOT + r3] = s.w;
    } else {
#pragma unroll
        for (int j = 0; j < 4; j++)
            if (b + j < E) {
                int d = dst[b + j];
                int r = atomicAdd(&g_cnt[d], 1);
                if (r < SLOT) g_csr[(size_t)d * SLOT + r] = src[b + j];
            }
    }
}

// ================= layer-1 GEMM: hs1 = (x @ W1) * rsqrt(deg) =================
// 128x64 tile, BK=32, 256 threads, 8x4 thread tile, packed f32x2 FMA.
// Xs m-major stride 33: conflict-free STS (consecutive threads vary k) and
// broadcast LDS.32 reads. Wd duplicated (w,w) u64, stride 17: conflict-free LDS.64.

__global__ __launch_bounds__(256) void k_gemm1(const float* __restrict__ x,
                                               const float* __restrict__ W1) {
    __shared__ float Xs[128][33];
    __shared__ unsigned long long Wd[32][68];
    const int tid  = threadIdx.x;
    const int tx   = tid & 15;      // 4 output cols
    const int ty   = tid >> 4;      // 8 output rows (4 row-pairs)
    const int row0 = blockIdx.x * 128;

    unsigned long long acc[4][4];   // [row-pair][col]
#pragma unroll
    for (int i = 0; i < 4; i++)
#pragma unroll
        for (int j = 0; j < 4; j++) acc[i][j] = 0ull;

    for (int k0 = 0; k0 < D_IN; k0 += 32) {
#pragma unroll
        for (int l = 0; l < 16; l++) {         // X: 128m x 32k, coalesced on k
            int idx = tid + l * 256;
            int m = idx >> 5, k = idx & 31;
            int row = row0 + m;
            Xs[m][k] = (row < N_NODES) ? x[(size_t)row * D_IN + k0 + k] : 0.f;
        }
#pragma unroll
        for (int l = 0; l < 8; l++) {          // W: 32k x 64n, duplicated-pack
            int idx = tid + l * 256;
            int k = idx >> 6, n = idx & 63;
            float w = W1[(size_t)(k0 + k) * D_H + n];
            Wd[k][(n & 3) * 17 + (n >> 2)] = pack2(w, w);
        }
        __syncthreads();
#pragma unroll
        for (int k = 0; k < 32; k++) {
            unsigned long long A[4];
#pragma unroll
            for (int i = 0; i < 4; i++)
                A[i] = pack2(Xs[ty * 8 + 2 * i][k], Xs[ty * 8 + 2 * i + 1][k]);
            unsigned long long b0 = Wd[k][0 * 17 + tx];
            unsigned long long b1 = Wd[k][1 * 17 + tx];
            unsigned long long b2 = Wd[k][2 * 17 + tx];
            unsigned long long b3 = Wd[k][3 * 17 + tx];
#pragma unroll
            for (int i = 0; i < 4; i++) {
                FFMA2(acc[i][0], A[i], b0, acc[i][0]);
                FFMA2(acc[i][1], A[i], b1, acc[i][1]);
                FFMA2(acc[i][2], A[i], b2, acc[i][2]);
                FFMA2(acc[i][3], A[i], b3, acc[i][3]);
            }
        }
        __syncthreads();
    }

#pragma unroll
    for (int i = 0; i < 4; i++) {
        float r0[4], r1[4];
#pragma unroll
        for (int j = 0; j < 4; j++) unpack2(acc[i][j], r0[j], r1[j]);
        int rowA = row0 + ty * 8 + 2 * i;
        int rowB = rowA + 1;
        if (rowA < N_NODES) {
            float di = rsqrtf((float)g_cnt[rowA] + 1.0f);
            float4 v = {r0[0] * di, r0[1] * di, r0[2] * di, r0[3] * di};
            *(float4*)&g_hs1[(size_t)rowA * D_H + tx * 4] = v;
        }
        if (rowB < N_NODES) {
            float di = rsqrtf((float)g_cnt[rowB] + 1.0f);
            float4 v = {r1[0] * di, r1[1] * di, r1[2] * di, r1[3] * di};
            *(float4*)&g_hs1[(size_t)rowB * D_H + tx * 4] = v;
        }
    }
}

// ================= fused layer-1 aggregation + relu + GEMV(W2) =================
// block = 256 threads = 16 nodes x 16 lanes; indices shfl-broadcast.

__global__ __launch_bounds__(256) void k_agg_node(const float* __restrict__ b1,
                                                  const float* __restrict__ W2) {
    __shared__ float sh [16][68];
    __shared__ float W2t[16][68];   // W2t[j][k] = W2[k][j]

    const int tid  = threadIdx.x;
    const int part = tid & 15;
    const int nl   = tid >> 4;
    const int n    = blockIdx.x * 16 + nl;
    const int lane = tid & 31;
    const int gb   = lane & 16;
    const unsigned gmask = 0xFFFFu << gb;

#pragma unroll
    for (int idx = tid; idx < D_H * D_OUT; idx += 256) {
        int k = idx >> 4, j = idx & 15;
        W2t[j][k] = W2[idx];
    }

    int cnt = g_cnt[n];
    if (cnt > SLOT) cnt = SLOT;
    const size_t off = (size_t)n * SLOT;

    const ulonglong2* base = (const ulonglong2*)g_hs1;
    ulonglong2 acc = base[(size_t)n * 16 + part];          // self-loop term

    for (int i = 0; i < cnt; i += 16) {
        int jm = cnt - i; if (jm > 16) jm = 16;            // uniform in group
        int idx = (part < jm) ? g_csr[off + i + part] : 0;
        for (int j = 0; j < jm; j++) {
            int s = __shfl_sync(gmask, idx, gb + j);
            ulonglong2 v = base[(size_t)s * 16 + part];
            FADD2(acc.x, acc.x, v.x);
            FADD2(acc.y, acc.y, v.y);
        }
    }

    float a0, a1, a2, a3;
    unpack2(acc.x, a0, a1);
    unpack2(acc.y, a2, a3);
    const float di = rsqrtf((float)g_cnt[n] + 1.0f);
    float4 bb = *(const float4*)&b1[part * 4];
    float4 r;
    r.x = fmaxf(fmaf(di, a0, bb.x), 0.f);
    r.y = fmaxf(fmaf(di, a1, bb.y), 0.f);
    r.z = fmaxf(fmaf(di, a2, bb.z), 0.f);
    r.w = fmaxf(fmaf(di, a3, bb.w), 0.f);
    *(float4*)&sh[nl][part * 4] = r;
    __syncthreads();

    float o = 0.f;
#pragma unroll
    for (int k4 = 0; k4 < D_H / 4; k4++) {
        float4 v4 = *(const float4*)&sh [nl]  [k4 * 4];
        float4 w4 = *(const float4*)&W2t[part][k4 * 4];
        o = fmaf(v4.x, w4.x, o);
        o = fmaf(v4.y, w4.y, o);
        o = fmaf(v4.z, w4.z, o);
        o = fmaf(v4.w, w4.w, o);
    }
    g_hs2[(size_t)n * D_OUT + part] = o * di;
}

// ================= layer-2 aggregation + epilogue; resets g_cnt =================
// 4 lanes per node; indices shfl-broadcast within 4-lane groups.

__global__ __launch_bounds__(256) void k_agg2(const float* __restrict__ b2,
                                              float* __restrict__ out) {
    long long t = (long long)blockIdx.x * blockDim.x + threadIdx.x;
    int n = (int)(t >> 2);
    const int valid = (n < N_NODES);
    if (!valid) n = N_NODES - 1;        // clamp (shfl safety)
    const int part = (int)(t & 3);
    const int lane = threadIdx.x & 31;
    const int gb4  = lane & ~3;
    const unsigned gmask = 0xFu << gb4;

    const int rawcnt = g_cnt[n];
    int cnt = rawcnt > SLOT ? SLOT : rawcnt;
    const size_t off = (size_t)n * SLOT;

    const ulonglong2* base = (const ulonglong2*)g_hs2;
    ulonglong2 acc = base[(size_t)n * 4 + part];           // self-loop term

    for (int i = 0; i < cnt; i += 4) {
        int jm = cnt - i; if (jm > 4) jm = 4;              // uniform in group
        int idx = (part < jm) ? g_csr[off + i + part] : 0;
        for (int j = 0; j < jm; j++) {
            int s = __shfl_sync(gmask, idx, gb4 + j);
            ulonglong2 v = base[(size_t)s * 4 + part];
            FADD2(acc.x, acc.x, v.x);
            FADD2(acc.y, acc.y, v.y);
        }
    }

    if (valid && part == 0) g_cnt[n] = 0;   // reset for next run (after reads)

    if (valid) {
        float a0, a1, a2, a3;
        unpack2(acc.x, a0, a1);
        unpack2(acc.y, a2, a3);
        float di = rsqrtf((float)rawcnt + 1.0f);
        float4 bb = *(const float4*)&b2[part * 4];
        float4 o = {fmaf(di, a0, bb.x), fmaf(di, a1, bb.y),
                    fmaf(di, a2, bb.z), fmaf(di, a3, bb.w)};
        *(float4*)&out[(size_t)n * D_OUT + part * 4] = o;
    }
}

// ================= launch =================

extern "C" void kernel_launch(void* const* d_in, const int* in_sizes, int n_in,
                              void* d_out, int out_size) {
    const float* x  = (const float*)d_in[0];
    const int*   ei = (const int*)  d_in[1];
    const float* W1 = (const float*)d_in[2];
    const float* b1 = (const float*)d_in[3];
    const float* W2 = (const float*)d_in[4];
    const float* b2 = (const float*)d_in[5];
    const int E = in_sizes[1] / 2;
    const int* src = ei;
    const int* dst = ei + E;

    int egrid4 = (E / 4 + 255) / 256 + 1;   // 4 edges/thread

    k_build   <<<egrid4, 256>>>(src, dst, E);
    k_gemm1   <<<(N_NODES + 127) / 128, 256>>>(x, W1);
    k_agg_node<<<N_NODES / 16, 256>>>(b1, W2);             // 100000/16 exact
    k_agg2    <<<(N_NODES * 4 + 255) / 256, 256>>>(b2, (float*)d_out);
}

// round 6
// speedup vs baseline: 1.1280x; 1.1280x over previous
#include <cuda_runtime.h>

#define N_NODES 100000
#define E_MAX   1600000
#define D_IN    128
#define D_H     64
#define D_OUT   16
#define SLOT    80          // fixed CSR slots per node (Poisson(16): P(deg>=80)~1e-28)

// ---- packed f32x2 helpers (sm_103a dual-lane fp32 pipe) ----
#define FFMA2(d, a, b, c) \
    asm("fma.rn.f32x2 %0, %1, %2, %3;" : "=l"(d) : "l"(a), "l"(b), "l"(c))
#define FADD2(d, a, b) \
    asm("add.rn.f32x2 %0, %1, %2;" : "=l"(d) : "l"(a), "l"(b))

__device__ __forceinline__ unsigned long long pack2(float lo, float hi) {
    unsigned long long r;
    asm("mov.b64 %0, {%1, %2};" : "=l"(r) : "f"(lo), "f"(hi));
    return r;
}
__device__ __forceinline__ void unpack2(unsigned long long v, float& lo, float& hi) {
    asm("mov.b64 {%0, %1}, %2;" : "=f"(lo), "=f"(hi) : "l"(v));
}

// ---- scratch (__device__ globals: allocation-free rule) ----
// g_cnt arrives zeroed (zero-init at load; re-zeroed by k_agg2 every run).
__device__ int   g_cnt[N_NODES];
__device__ int   g_csr[(size_t)N_NODES * SLOT];
__device__ float g_hs1[(size_t)N_NODES * D_H];
__device__ float g_hs2[(size_t)N_NODES * D_OUT];

// ================= single-pass slotted CSR build =================

__global__ void k_build(const int* __restrict__ src, const int* __restrict__ dst, int E) {
    int b = (blockIdx.x * blockDim.x + threadIdx.x) * 4;
    if (b + 3 < E && ((E & 3) == 0)) {
        int4 s = *(const int4*)&src[b];
        int4 d = *(const int4*)&dst[b];
        int r0 = atomicAdd(&g_cnt[d.x], 1);
        int r1 = atomicAdd(&g_cnt[d.y], 1);
        int r2 = atomicAdd(&g_cnt[d.z], 1);
        int r3 = atomicAdd(&g_cnt[d.w], 1);
        if (r0 < SLOT) g_csr[(size_t)d.x * SLOT + r0] = s.x;
        if (r1 < SLOT) g_csr[(size_t)d.y * SLOT + r1] = s.y;
        if (r2 < SLOT) g_csr[(size_t)d.z * SLOT + r2] = s.z;
        if (r3 < SLOT) g_csr[(size_t)d.w * SLOT + r3] = s.w;
    } else {
#pragma unroll
        for (int j = 0; j < 4; j++)
            if (b + j < E) {
                int d = dst[b + j];
                int r = atomicAdd(&g_cnt[d], 1);
                if (r < SLOT) g_csr[(size_t)d * SLOT + r] = src[b + j];
            }
    }
}

// ================= layer-1 GEMM: hs1 = (x @ W1) * rsqrt(deg) =================
// 128x64 tile, BK=32, 256 threads, 8x4 thread tile, packed f32x2 FMA.
// Xs m-major stride 33: conflict-free STS and broadcast LDS.
// Wd duplicated (w,w) u64, stride 17: conflict-free LDS.64.

__global__ __launch_bounds__(256) void k_gemm1(const float* __restrict__ x,
                                               const float* __restrict__ W1) {
    __shared__ float Xs[128][33];
    __shared__ unsigned long long Wd[32][68];
    const int tid  = threadIdx.x;
    const int tx   = tid & 15;      // 4 output cols
    const int ty   = tid >> 4;      // 8 output rows (4 row-pairs)
    const int row0 = blockIdx.x * 128;

    unsigned long long acc[4][4];
#pragma unroll
    for (int i = 0; i < 4; i++)
#pragma unroll
        for (int j = 0; j < 4; j++) acc[i][j] = 0ull;

    for (int k0 = 0; k0 < D_IN; k0 += 32) {
#pragma unroll
        for (int l = 0; l < 16; l++) {         // X: 128m x 32k, coalesced on k
            int idx = tid + l * 256;
            int m = idx >> 5, k = idx & 31;
            int row = row0 + m;
            Xs[m][k] = (row < N_NODES) ? x[(size_t)row * D_IN + k0 + k] : 0.f;
        }
#pragma unroll
        for (int l = 0; l < 8; l++) {          // W: 32k x 64n, duplicated-pack
            int idx = tid + l * 256;
            int k = idx >> 6, n = idx & 63;
            float w = W1[(size_t)(k0 + k) * D_H + n];
            Wd[k][(n & 3) * 17 + (n >> 2)] = pack2(w, w);
        }
        __syncthreads();
#pragma unroll
        for (int k = 0; k < 32; k++) {
            unsigned long long A[4];
#pragma unroll
            for (int i = 0; i < 4; i++)
                A[i] = pack2(Xs[ty * 8 + 2 * i][k], Xs[ty * 8 + 2 * i + 1][k]);
            unsigned long long b0 = Wd[k][0 * 17 + tx];
            unsigned long long b1 = Wd[k][1 * 17 + tx];
            unsigned long long b2 = Wd[k][2 * 17 + tx];
            unsigned long long b3 = Wd[k][3 * 17 + tx];
#pragma unroll
            for (int i = 0; i < 4; i++) {
                FFMA2(acc[i][0], A[i], b0, acc[i][0]);
                FFMA2(acc[i][1], A[i], b1, acc[i][1]);
                FFMA2(acc[i][2], A[i], b2, acc[i][2]);
                FFMA2(acc[i][3], A[i], b3, acc[i][3]);
            }
        }
        __syncthreads();
    }

#pragma unroll
    for (int i = 0; i < 4; i++) {
        float r0[4], r1[4];
#pragma unroll
        for (int j = 0; j < 4; j++) unpack2(acc[i][j], r0[j], r1[j]);
        int rowA = row0 + ty * 8 + 2 * i;
        int rowB = rowA + 1;
        if (rowA < N_NODES) {
            float di = rsqrtf((float)g_cnt[rowA] + 1.0f);
            float4 v = {r0[0] * di, r0[1] * di, r0[2] * di, r0[3] * di};
            *(float4*)&g_hs1[(size_t)rowA * D_H + tx * 4] = v;
        }
        if (rowB < N_NODES) {
            float di = rsqrtf((float)g_cnt[rowB] + 1.0f);
            float4 v = {r1[0] * di, r1[1] * di, r1[2] * di, r1[3] * di};
            *(float4*)&g_hs1[(size_t)rowB * D_H + tx * 4] = v;
        }
    }
}

// ================= fused layer-1 aggregation + relu + GEMV(W2) =================
// block = 256 threads = 16 nodes x 16 lanes; indices shfl-broadcast.
// Inner loop FULLY UNROLLED with predication -> 16 LDGs in flight (MLP).

__global__ __launch_bounds__(256) void k_agg_node(const float* __restrict__ b1,
                                                  const float* __restrict__ W2) {
    __shared__ float sh [16][68];
    __shared__ float W2t[16][68];   // W2t[j][k] = W2[k][j]

    const int tid  = threadIdx.x;
    const int part = tid & 15;
    const int nl   = tid >> 4;
    const int n    = blockIdx.x * 16 + nl;
    const int lane = tid & 31;
    const int gb   = lane & 16;
    const unsigned gmask = 0xFFFFu << gb;

#pragma unroll
    for (int idx = tid; idx < D_H * D_OUT; idx += 256) {
        int k = idx >> 4, j = idx & 15;
        W2t[j][k] = W2[idx];
    }

    int cnt = g_cnt[n];
    if (cnt > SLOT) cnt = SLOT;
    const size_t off = (size_t)n * SLOT;

    const ulonglong2* base = (const ulonglong2*)g_hs1;
    ulonglong2 acc = base[(size_t)n * 16 + part];          // self-loop term

    for (int i = 0; i < cnt; i += 16) {
        int idx = (i + part < cnt) ? g_csr[off + i + part] : 0;
#pragma unroll
        for (int j = 0; j < 16; j++) {
            int s = __shfl_sync(gmask, idx, gb + j);
            if (i + j < cnt) {
                ulonglong2 v = base[(size_t)s * 16 + part];
                FADD2(acc.x, acc.x, v.x);
                FADD2(acc.y, acc.y, v.y);
            }
        }
    }

    float a0, a1, a2, a3;
    unpack2(acc.x, a0, a1);
    unpack2(acc.y, a2, a3);
    const float di = rsqrtf((float)g_cnt[n] + 1.0f);
    float4 bb = *(const float4*)&b1[part * 4];
    float4 r;
    r.x = fmaxf(fmaf(di, a0, bb.x), 0.f);
    r.y = fmaxf(fmaf(di, a1, bb.y), 0.f);
    r.z = fmaxf(fmaf(di, a2, bb.z), 0.f);
    r.w = fmaxf(fmaf(di, a3, bb.w), 0.f);
    *(float4*)&sh[nl][part * 4] = r;
    __syncthreads();

    float o = 0.f;
#pragma unroll
    for (int k4 = 0; k4 < D_H / 4; k4++) {
        float4 v4 = *(const float4*)&sh [nl]  [k4 * 4];
        float4 w4 = *(const float4*)&W2t[part][k4 * 4];
        o = fmaf(v4.x, w4.x, o);
        o = fmaf(v4.y, w4.y, o);
        o = fmaf(v4.z, w4.z, o);
        o = fmaf(v4.w, w4.w, o);
    }
    g_hs2[(size_t)n * D_OUT + part] = o * di;
}

// ================= layer-2 aggregation + epilogue; resets g_cnt =================
// 4 lanes per node; unrolled 2 outer x 4 inner -> 8 LDGs in flight.

__global__ __launch_bounds__(256) void k_agg2(const float* __restrict__ b2,
                                              float* __restrict__ out) {
    long long t = (long long)blockIdx.x * blockDim.x + threadIdx.x;
    int n = (int)(t >> 2);
    const int valid = (n < N_NODES);
    if (!valid) n = N_NODES - 1;        // clamp (shfl safety)
    const int part = (int)(t & 3);
    const int lane = threadIdx.x & 31;
    const int gb4  = lane & ~3;
    const unsigned gmask = 0xFu << gb4;

    const int rawcnt = g_cnt[n];
    int cnt = rawcnt > SLOT ? SLOT : rawcnt;
    const size_t off = (size_t)n * SLOT;

    const ulonglong2* base = (const ulonglong2*)g_hs2;
    ulonglong2 acc = base[(size_t)n * 4 + part];           // self-loop term

    for (int i = 0; i < cnt; i += 8) {
        int i0 = i + part;
        int i1 = i + 4 + part;
        int idxA = (i0 < cnt) ? g_csr[off + i0] : 0;
        int idxB = (i1 < cnt) ? g_csr[off + i1] : 0;
#pragma unroll
        for (int j = 0; j < 4; j++) {
            int s = __shfl_sync(gmask, idxA, gb4 + j);
            if (i + j < cnt) {
                ulonglong2 v = base[(size_t)s * 4 + part];
                FADD2(acc.x, acc.x, v.x);
                FADD2(acc.y, acc.y, v.y);
            }
        }
#pragma unroll
        for (int j = 0; j < 4; j++) {
            int s = __shfl_sync(gmask, idxB, gb4 + j);
            if (i + 4 + j < cnt) {
                ulonglong2 v = base[(size_t)s * 4 + part];
                FADD2(acc.x, acc.x, v.x);
                FADD2(acc.y, acc.y, v.y);
            }
        }
    }

    if (valid && part == 0) g_cnt[n] = 0;   // reset for next run (after reads)

    if (valid) {
        float a0, a1, a2, a3;
        unpack2(acc.x, a0, a1);
        unpack2(acc.y, a2, a3);
        float di = rsqrtf((float)rawcnt + 1.0f);
        float4 bb = *(const float4*)&b2[part * 4];
        float4 o = {fmaf(di, a0, bb.x), fmaf(di, a1, bb.y),
                    fmaf(di, a2, bb.z), fmaf(di, a3, bb.w)};
        *(float4*)&out[(size_t)n * D_OUT + part * 4] = o;
    }
}

// ================= launch =================

extern "C" void kernel_launch(void* const* d_in, const int* in_sizes, int n_in,
                              void* d_out, int out_size) {
    const float* x  = (const float*)d_in[0];
    const int*   ei = (const int*)  d_in[1];
    const float* W1 = (const float*)d_in[2];
    const float* b1 = (const float*)d_in[3];
    const float* W2 = (const float*)d_in[4];
    const float* b2 = (const float*)d_in[5];
    const int E = in_sizes[1] / 2;
    const int* src = ei;
    const int* dst = ei + E;

    int egrid4 = (E / 4 + 255) / 256 + 1;   // 4 edges/thread

    k_build   <<<egrid4, 256>>>(src, dst, E);
    k_gemm1   <<<(N_NODES + 127) / 128, 256>>>(x, W1);
    k_agg_node<<<N_NODES / 16, 256>>>(b1, W2);             // 100000/16 exact
    k_agg2    <<<(N_NODES * 4 + 255) / 256, 256>>>(b2, (float*)d_out);
}

// round 7
// speedup vs baseline: 1.2839x; 1.1382x over previous
#include <cuda_runtime.h>

#define N_NODES 100000
#define E_MAX   1600000
#define D_IN    128
#define D_H     64
#define D_OUT   16
#define SLOT    80          // fixed CSR slots per node (Poisson(16): P(deg>=80)~1e-28)

// ---- packed f32x2 helpers (sm_103a dual-lane fp32 pipe) ----
#define FFMA2(d, a, b, c) \
    asm("fma.rn.f32x2 %0, %1, %2, %3;" : "=l"(d) : "l"(a), "l"(b), "l"(c))
#define FADD2(d, a, b) \
    asm("add.rn.f32x2 %0, %1, %2;" : "=l"(d) : "l"(a), "l"(b))
#define FMUL2(d, a, b) \
    asm("mul.rn.f32x2 %0, %1, %2;" : "=l"(d) : "l"(a), "l"(b))

__device__ __forceinline__ unsigned long long pack2(float lo, float hi) {
    unsigned long long r;
    asm("mov.b64 %0, {%1, %2};" : "=l"(r) : "f"(lo), "f"(hi));
    return r;
}
__device__ __forceinline__ void unpack2(unsigned long long v, float& lo, float& hi) {
    asm("mov.b64 {%0, %1}, %2;" : "=f"(lo), "=f"(hi) : "l"(v));
}

// ---- scratch (__device__ globals: allocation-free rule) ----
// g_cnt arrives zeroed (zero-init at load; re-zeroed by k_agg2 every run).
__device__ int   g_cnt[N_NODES];
__device__ int   g_csr[(size_t)N_NODES * SLOT];
__device__ float g_hs1[(size_t)N_NODES * D_H];    // UNSCALED x@W1
__device__ float g_hs2[(size_t)N_NODES * D_OUT];  // dinv-scaled layer-2 features

// ================= fat kernel: CSR build + layer-1 GEMM, interleaved =================
// gemm writes UNSCALED hs1 (no g_cnt read) -> build & gemm blocks are fully
// independent and overlap: build saturates LSU/atomics, gemm saturates FMA.

__device__ __forceinline__ void build_body(const int* __restrict__ src,
                                           const int* __restrict__ dst,
                                           int E, int bid) {
    int b = (bid * 256 + threadIdx.x) * 4;
    if (b + 3 < E && ((E & 3) == 0)) {
        int4 s = *(const int4*)&src[b];
        int4 d = *(const int4*)&dst[b];
        int r0 = atomicAdd(&g_cnt[d.x], 1);
        int r1 = atomicAdd(&g_cnt[d.y], 1);
        int r2 = atomicAdd(&g_cnt[d.z], 1);
        int r3 = atomicAdd(&g_cnt[d.w], 1);
        if (r0 < SLOT) g_csr[(size_t)d.x * SLOT + r0] = s.x;
        if (r1 < SLOT) g_csr[(size_t)d.y * SLOT + r1] = s.y;
        if (r2 < SLOT) g_csr[(size_t)d.z * SLOT + r2] = s.z;
        if (r3 < SLOT) g_csr[(size_t)d.w * SLOT + r3] = s.w;
    } else {
#pragma unroll
        for (int j = 0; j < 4; j++)
            if (b + j < E) {
                int d = dst[b + j];
                int r = atomicAdd(&g_cnt[d], 1);
                if (r < SLOT) g_csr[(size_t)d * SLOT + r] = src[b + j];
            }
    }
}

__global__ __launch_bounds__(256) void k_build_gemm(const float* __restrict__ x,
                                                    const float* __restrict__ W1,
                                                    const int* __restrict__ src,
                                                    const int* __restrict__ dst,
                                                    int E, int gb, int total) {
    // Bresenham interleave: spread gb gemm blocks uniformly over [0,total)
    const int bid  = blockIdx.x;
    const int g_lo = (int)(((long long)bid * gb) / total);
    const int g_hi = (int)(((long long)(bid + 1) * gb) / total);

    if (g_hi == g_lo) {                 // ---- build block ----
        build_body(src, dst, E, bid - g_lo);
        return;
    }

    // ---- gemm block: 128x64 tile, BK=32, 8x4 thread tile, FFMA2 ----
    __shared__ unsigned long long Xs2[64][33];  // [m-pair][k], broadcast LDS.64
    __shared__ unsigned long long Wd [32][68];  // dup (w,w), stride-17 layout

    const int tid  = threadIdx.x;
    const int tx   = tid & 15;      // 4 output cols
    const int ty   = tid >> 4;      // 4 row-pairs (8 rows)
    const int row0 = g_lo * 128;

    unsigned long long acc[4][4];
#pragma unroll
    for (int i = 0; i < 4; i++)
#pragma unroll
        for (int j = 0; j < 4; j++) acc[i][j] = 0ull;

    for (int k0 = 0; k0 < D_IN; k0 += 32) {
#pragma unroll
        for (int l = 0; l < 8; l++) {          // X: 64 m-pairs x 32 k
            int idx = tid + l * 256;
            int k = idx & 31, mp = idx >> 5;
            int rA = row0 + 2 * mp;
            float lo = (rA     < N_NODES) ? x[(size_t)rA * D_IN + k0 + k]       : 0.f;
            float hi = (rA + 1 < N_NODES) ? x[(size_t)(rA + 1) * D_IN + k0 + k] : 0.f;
            Xs2[mp][k] = pack2(lo, hi);
        }
#pragma unroll
        for (int l = 0; l < 8; l++) {          // W: 32k x 64n duplicated-pack
            int idx = tid + l * 256;
            int k = idx >> 6, n = idx & 63;
            float w = W1[(size_t)(k0 + k) * D_H + n];
            Wd[k][(n & 3) * 17 + (n >> 2)] = pack2(w, w);
        }
        __syncthreads();
#pragma unroll
        for (int k = 0; k < 32; k++) {
            unsigned long long A0 = Xs2[ty * 4 + 0][k];
            unsigned long long A1 = Xs2[ty * 4 + 1][k];
            unsigned long long A2 = Xs2[ty * 4 + 2][k];
            unsigned long long A3 = Xs2[ty * 4 + 3][k];
            unsigned long long b0 = Wd[k][0 * 17 + tx];
            unsigned long long b1 = Wd[k][1 * 17 + tx];
            unsigned long long b2 = Wd[k][2 * 17 + tx];
            unsigned long long b3 = Wd[k][3 * 17 + tx];
            FFMA2(acc[0][0], A0, b0, acc[0][0]);
            FFMA2(acc[0][1], A0, b1, acc[0][1]);
            FFMA2(acc[0][2], A0, b2, acc[0][2]);
            FFMA2(acc[0][3], A0, b3, acc[0][3]);
            FFMA2(acc[1][0], A1, b0, acc[1][0]);
            FFMA2(acc[1][1], A1, b1, acc[1][1]);
            FFMA2(acc[1][2], A1, b2, acc[1][2]);
            FFMA2(acc[1][3], A1, b3, acc[1][3]);
            FFMA2(acc[2][0], A2, b0, acc[2][0]);
            FFMA2(acc[2][1], A2, b1, acc[2][1]);
            FFMA2(acc[2][2], A2, b2, acc[2][2]);
            FFMA2(acc[2][3], A2, b3, acc[2][3]);
            FFMA2(acc[3][0], A3, b0, acc[3][0]);
            FFMA2(acc[3][1], A3, b1, acc[3][1]);
            FFMA2(acc[3][2], A3, b2, acc[3][2]);
            FFMA2(acc[3][3], A3, b3, acc[3][3]);
        }
        __syncthreads();
    }

#pragma unroll
    for (int i = 0; i < 4; i++) {
        float r0[4], r1[4];
#pragma unroll
        for (int j = 0; j < 4; j++) unpack2(acc[i][j], r0[j], r1[j]);
        int rowA = row0 + ty * 8 + 2 * i;   // NOTE: thread owns rows pair (ty*4+i)
        rowA = row0 + (ty * 4 + i) * 2;
        int rowB = rowA + 1;
        if (rowA < N_NODES) {
            float4 v = {r0[0], r0[1], r0[2], r0[3]};
            *(float4*)&g_hs1[(size_t)rowA * D_H + tx * 4] = v;
        }
        if (rowB < N_NODES) {
            float4 v = {r1[0], r1[1], r1[2], r1[3]};
            *(float4*)&g_hs1[(size_t)rowB * D_H + tx * 4] = v;
        }
    }
}

// ================= fused layer-1 aggregation + relu + GEMV(W2) =================
// 16 nodes x 16 lanes per block. hs1 is unscaled: each gathered row is scaled
// by dinv[s] (owner lane computes rsqrt, shfl-broadcast alongside the index).

__global__ __launch_bounds__(256) void k_agg_node(const float* __restrict__ b1,
                                                  const float* __restrict__ W2) {
    __shared__ float sh [16][68];
    __shared__ float W2t[16][68];   // W2t[j][k] = W2[k][j]

    const int tid  = threadIdx.x;
    const int part = tid & 15;
    const int nl   = tid >> 4;
    const int n    = blockIdx.x * 16 + nl;
    const int lane = tid & 31;
    const int gb   = lane & 16;
    const unsigned gmask = 0xFFFFu << gb;

#pragma unroll
    for (int idx = tid; idx < D_H * D_OUT; idx += 256) {
        int k = idx >> 4, j = idx & 15;
        W2t[j][k] = W2[idx];
    }

    const int cnt_n = g_cnt[n];
    int cnt = cnt_n > SLOT ? SLOT : cnt_n;
    const float dn = rsqrtf((float)cnt_n + 1.0f);
    const size_t off = (size_t)n * SLOT;

    const ulonglong2* base = (const ulonglong2*)g_hs1;
    ulonglong2 self = base[(size_t)n * 16 + part];
    unsigned long long ddn = pack2(dn, dn);
    ulonglong2 acc;
    FMUL2(acc.x, self.x, ddn);          // self-loop: dinv_n * h_n
    FMUL2(acc.y, self.y, ddn);

    for (int i = 0; i < cnt; i += 16) {
        int   idx = 0;
        float ds  = 0.f;
        if (i + part < cnt) {
            idx = g_csr[off + i + part];
            ds  = rsqrtf((float)g_cnt[idx] + 1.0f);
        }
#pragma unroll
        for (int j = 0; j < 16; j++) {
            int   s   = __shfl_sync(gmask, idx, gb + j);
            float dsj = __shfl_sync(gmask, ds,  gb + j);
            if (i + j < cnt) {
                ulonglong2 v = base[(size_t)s * 16 + part];
                unsigned long long dd = pack2(dsj, dsj);
                FFMA2(acc.x, v.x, dd, acc.x);
                FFMA2(acc.y, v.y, dd, acc.y);
            }
        }
    }

    float a0, a1, a2, a3;
    unpack2(acc.x, a0, a1);
    unpack2(acc.y, a2, a3);
    float4 bb = *(const float4*)&b1[part * 4];
    float4 r;
    r.x = fmaxf(fmaf(dn, a0, bb.x), 0.f);
    r.y = fmaxf(fmaf(dn, a1, bb.y), 0.f);
    r.z = fmaxf(fmaf(dn, a2, bb.z), 0.f);
    r.w = fmaxf(fmaf(dn, a3, bb.w), 0.f);
    *(float4*)&sh[nl][part * 4] = r;
    __syncthreads();

    float o = 0.f;
#pragma unroll
    for (int k4 = 0; k4 < D_H / 4; k4++) {
        float4 v4 = *(const float4*)&sh [nl]  [k4 * 4];
        float4 w4 = *(const float4*)&W2t[part][k4 * 4];
        o = fmaf(v4.x, w4.x, o);
        o = fmaf(v4.y, w4.y, o);
        o = fmaf(v4.z, w4.z, o);
        o = fmaf(v4.w, w4.w, o);
    }
    g_hs2[(size_t)n * D_OUT + part] = o * dn;   // pre-scaled by dinv_n
}

// ================= layer-2 aggregation + epilogue; resets g_cnt =================
// 4 lanes per node; hs2 rows already dinv-scaled -> plain adds.

__global__ __launch_bounds__(256) void k_agg2(const float* __restrict__ b2,
                                              float* __restrict__ out) {
    long long t = (long long)blockIdx.x * blockDim.x + threadIdx.x;
    int n = (int)(t >> 2);
    const int valid = (n < N_NODES);
    if (!valid) n = N_NODES - 1;        // clamp (shfl safety)
    const int part = (int)(t & 3);
    const int lane = threadIdx.x & 31;
    const int gb4  = lane & ~3;
    const unsigned gmask = 0xFu << gb4;

    const int rawcnt = g_cnt[n];
    int cnt = rawcnt > SLOT ? SLOT : rawcnt;
    const size_t off = (size_t)n * SLOT;

    const ulonglong2* base = (const ulonglong2*)g_hs2;
    ulonglong2 acc = base[(size_t)n * 4 + part];           // self-loop term

    for (int i = 0; i < cnt; i += 8) {
        int i0 = i + part;
        int i1 = i + 4 + part;
        int idxA = (i0 < cnt) ? g_csr[off + i0] : 0;
        int idxB = (i1 < cnt) ? g_csr[off + i1] : 0;
#pragma unroll
        for (int j = 0; j < 4; j++) {
            int s = __shfl_sync(gmask, idxA, gb4 + j);
            if (i + j < cnt) {
                ulonglong2 v = base[(size_t)s * 4 + part];
                FADD2(acc.x, acc.x, v.x);
                FADD2(acc.y, acc.y, v.y);
            }
        }
#pragma unroll
        for (int j = 0; j < 4; j++) {
            int s = __shfl_sync(gmask, idxB, gb4 + j);
            if (i + 4 + j < cnt) {
                ulonglong2 v = base[(size_t)s * 4 + part];
                FADD2(acc.x, acc.x, v.x);
                FADD2(acc.y, acc.y, v.y);
            }
        }
    }

    if (valid && part == 0) g_cnt[n] = 0;   // reset for next run (after reads)

    if (valid) {
        float a0, a1, a2, a3;
        unpack2(acc.x, a0, a1);
        unpack2(acc.y, a2, a3);
        float di = rsqrtf((float)rawcnt + 1.0f);
        float4 bb = *(const float4*)&b2[part * 4];
        float4 o = {fmaf(di, a0, bb.x), fmaf(di, a1, bb.y),
                    fmaf(di, a2, bb.z), fmaf(di, a3, bb.w)};
        *(float4*)&out[(size_t)n * D_OUT + part * 4] = o;
    }
}

// ================= launch =================

extern "C" void kernel_launch(void* const* d_in, const int* in_sizes, int n_in,
                              void* d_out, int out_size) {
    const float* x  = (const float*)d_in[0];
    const int*   ei = (const int*)  d_in[1];
    const float* W1 = (const float*)d_in[2];
    const float* b1 = (const float*)d_in[3];
    const float* W2 = (const float*)d_in[4];
    const float* b2 = (const float*)d_in[5];
    const int E = in_sizes[1] / 2;
    const int* src = ei;
    const int* dst = ei + E;

    const int gemm_blocks  = (N_NODES + 127) / 128;        // 782
    const int build_blocks = (E / 4 + 255) / 256 + 1;      // 1564
    const int total        = gemm_blocks + build_blocks;

    k_build_gemm<<<total, 256>>>(x, W1, src, dst, E, gemm_blocks, total);
    k_agg_node  <<<N_NODES / 16, 256>>>(b1, W2);            // 100000/16 exact
    k_agg2      <<<(N_NODES * 4 + 255) / 256, 256>>>(b2, (float*)d_out);
}